// round 13
// baseline (speedup 1.0000x reference)
#include <cuda_runtime.h>
#include <cstddef>

// Problem constants (from reference setup_inputs)
#define TT   1000
#define BB   8192
#define IN   4
#define HID  10
#define OUT  3
#define BETA 0.95f
#define THR  1.0f

#define NLUT (1 << HID)      // 1024 possible spk1 patterns
#define B3   (BB * OUT)      // floats per timestep per output array
#define EPW  3               // elements per warp (10 lanes each; lanes 30,31 dummy)
#define NWARPS 2732          // ceil(8192/3) rounded to even (2 warps/block)
#define NBLOCKS (NWARPS / 2) // 1366 blocks of 64 threads

// One lane = one hidden unit. Warp w handles elements w*3+{0,1,2}; lane
// eidx*10+h runs LIF unit h of element eidx. spk1 mask assembled with ONE
// __ballot_sync. Lane h<3 also runs layer-2 output unit h and stores its
// spk+mem pair. ~4.6 warps/SMSP so each warp's serial stalls are hidden by
// co-resident warps (R10 showed co-residency is contention-free).
__global__ __launch_bounds__(64, 1)
void snn_lif_kernel(const float* __restrict__ x,
                    const float* __restrict__ W1,
                    const float* __restrict__ b1,
                    const float* __restrict__ W2,
                    const float* __restrict__ b2,
                    float* __restrict__ out)
{
    // LUT: cur2 = W2 @ spk1 + b2 for every possible spk1 bitmask.
    // Ascending-h subset sum, separately-rounded adds, bias last —
    // bit-identical to the reference 0/1 dot under fma OR mul+add lowering.
    __shared__ float4 lut[NLUT];
    for (int m = threadIdx.x; m < NLUT; m += blockDim.x) {
        float c0 = 0.f, c1 = 0.f, c2 = 0.f;
        #pragma unroll
        for (int h = 0; h < HID; ++h) {
            if (m & (1 << h)) {
                c0 = __fadd_rn(c0, W2[0 * HID + h]);
                c1 = __fadd_rn(c1, W2[1 * HID + h]);
                c2 = __fadd_rn(c2, W2[2 * HID + h]);
            }
        }
        c0 = __fadd_rn(c0, b2[0]);
        c1 = __fadd_rn(c1, b2[1]);
        c2 = __fadd_rn(c2, b2[2]);
        lut[m] = make_float4(c0, c1, c2, 0.f);
    }
    __syncthreads();

    const int wg    = blockIdx.x * 2 + (threadIdx.x >> 5);  // global warp id
    const int lane  = threadIdx.x & 31;
    const int eidx  = lane / 10;          // 0..2 real, 3 = dummy lanes 30,31
    const int h     = lane - eidx * 10;   // unit id 0..9
    const bool dummy = (eidx == 3);
    const int e     = wg * EPW + (dummy ? 0 : eidx);
    const bool evalid = (e < BB) && !dummy;
    const int e_ld  = evalid ? e : 0;     // clamp loads for dummy/overflow
    const unsigned shift = eidx * 10;     // ballot field for my element

    // This lane's unit weights.
    const float w0 = W1[h * IN + 0], w1 = W1[h * IN + 1];
    const float w2 = W1[h * IN + 2], w3 = W1[h * IN + 3];
    const float bb = b1[h];

    // State (layer-2 state is junk on lanes h>=3; never stored).
    // Prev-spike kept as {-1, 0} float so reset is one always-executed add
    // (adding -0.0f is the identity => bit-exact).
    float m1 = 0.f, s1 = 0.f;
    float m2 = 0.f, s2 = 0.f;

    const float4* __restrict__ xp = reinterpret_cast<const float4*>(x) + e_ld;
    // Lane h<3 of a valid element writes spk2[t,e,h] and mem2[t,e,h].
    float* __restrict__ ps = out + (size_t)e * OUT + h;                   // spk2
    float* __restrict__ pm = out + (size_t)TT * B3 + (size_t)e * OUT + h; // mem2
    const bool wr = evalid && (h < OUT);

    // Prefetch ring: x[t..t+3] resident (10 lanes share each element's
    // float4 — L1 broadcast; DRAM sees unique lines).
    float4 xbuf[4];
    #pragma unroll
    for (int k = 0; k < 4; ++k) xbuf[k] = xp[(size_t)k * BB];

    for (int t = 0; t < TT; t += 4) {
        // Prefetch x[t+4..t+7] (tail clamps to x[0..3]; those values feed
        // only discarded junk past step TT-1).
        const float4* xq = (t + 4 < TT) ? (xp + (size_t)(t + 4) * BB) : xp;
        float4 nxt[4];
        #pragma unroll
        for (int k = 0; k < 4; ++k) nxt[k] = xq[(size_t)k * BB];

        #pragma unroll
        for (int k = 0; k < 4; ++k) {
            const float4 xv = xbuf[k];

            // ---- Layer 1: this lane's single LIF unit ----
            // Ascending-k, separate mul/add roundings (no fma), bias last.
            float c = __fmul_rn(xv.x, w0);
            c = __fadd_rn(c, __fmul_rn(xv.y, w1));
            c = __fadd_rn(c, __fmul_rn(xv.z, w2));
            c = __fadd_rn(c, __fmul_rn(xv.w, w3));
            c = __fadd_rn(c, bb);
            float m = __fadd_rn(__fmul_rn(BETA, m1), c);  // beta*mem + cur
            m = __fadd_rn(m, s1);                          // + (-reset*THR)
            const bool sp = m > THR;
            s1 = sp ? -1.0f : 0.0f;
            m1 = m;

            // ---- Assemble spk1 mask: ONE ballot for all 3 elements ----
            const unsigned bal  = __ballot_sync(0xFFFFFFFFu, sp);
            const unsigned mask = (bal >> shift) & 0x3FFu;

            // ---- Layer 2: lane h (<3) owns output unit h ----
            const float4 cv = lut[mask];
            const float cc = (h == 0) ? cv.x : ((h == 1) ? cv.y : cv.z);
            float mm = __fadd_rn(__fmul_rn(BETA, m2), cc);
            mm = __fadd_rn(mm, s2);
            const bool sp2 = mm > THR;
            s2 = sp2 ? -1.0f : 0.0f;
            m2 = mm;

            if (wr) {
                const size_t off = (size_t)(t + k) * B3;
                ps[off] = sp2 ? 1.0f : 0.0f;   // spk2_rec[t+k, e, h]
                pm[off] = mm;                   // mem2_rec[t+k, e, h]
            }
        }

        #pragma unroll
        for (int k = 0; k < 4; ++k) xbuf[k] = nxt[k];
    }
}

extern "C" void kernel_launch(void* const* d_in, const int* in_sizes, int n_in,
                              void* d_out, int out_size)
{
    const float* x  = (const float*)d_in[0];   // [1000, 8192, 4]
    const float* W1 = (const float*)d_in[1];   // [10, 4]
    const float* b1 = (const float*)d_in[2];   // [10]
    const float* W2 = (const float*)d_in[3];   // [3, 10]
    const float* b2 = (const float*)d_in[4];   // [3]
    float* out = (float*)d_out;                // [spk2_rec | mem2_rec]

    snn_lif_kernel<<<NBLOCKS, 64>>>(x, W1, b1, W2, b2, out);
}

// round 17
// speedup vs baseline: 1.3804x; 1.3804x over previous
#include <cuda_runtime.h>
#include <cstddef>

// Problem constants (from reference setup_inputs)
#define TT   1000
#define BB   8192
#define IN   4
#define HID  10
#define OUT  3
#define BETA 0.95f
#define THR  1.0f

#define NLUT (1 << HID)      // 1024 possible spk1 patterns
#define B3   (BB * OUT)      // floats per timestep per output array
#define HHALF 5              // hidden units per thread-half

// Spike test on the alu pipe: m > 1.0f  <=>  bits(m) > bits(1.0f) as signed
// ints (positives monotone; negatives/±0 map below; NaN unreachable here).
__device__ __forceinline__ bool spike_gt1(float m) {
    return __float_as_int(m) > 0x3F800000;
}

// Two threads per batch element. 64 blocks x 256 threads = 16384 threads
// = 2 warps/SMSP on 64 SMs (R10 config: fma-pipe-bound regime).
// This round evicts non-arithmetic ops from the fma pipe: ISETP compares,
// predicated reset-add (no SEL), predicated mask OR.
__global__ __launch_bounds__(256, 1)
void snn_lif_kernel(const float* __restrict__ x,
                    const float* __restrict__ W1,
                    const float* __restrict__ b1,
                    const float* __restrict__ W2,
                    const float* __restrict__ b2,
                    float* __restrict__ out)
{
    // LUT: cur2 = W2 @ spk1 + b2 for every possible spk1 bitmask.
    // Ascending-h subset sum, separately-rounded adds, bias last —
    // bit-identical to the reference 0/1 dot under fma OR mul+add lowering.
    __shared__ float4 lut[NLUT];
    for (int m = threadIdx.x; m < NLUT; m += blockDim.x) {
        float c0 = 0.f, c1 = 0.f, c2 = 0.f;
        #pragma unroll
        for (int h = 0; h < HID; ++h) {
            if (m & (1 << h)) {
                c0 = __fadd_rn(c0, W2[0 * HID + h]);
                c1 = __fadd_rn(c1, W2[1 * HID + h]);
                c2 = __fadd_rn(c2, W2[2 * HID + h]);
            }
        }
        c0 = __fadd_rn(c0, b2[0]);
        c1 = __fadd_rn(c1, b2[1]);
        c2 = __fadd_rn(c2, b2[2]);
        lut[m] = make_float4(c0, c1, c2, 0.f);
    }

    const int tid   = blockIdx.x * blockDim.x + threadIdx.x;
    const int e     = tid >> 1;        // batch element
    const int half  = tid & 1;         // which 5 hidden units
    const int hbase = half * HHALF;

    // This half's layer-1 weights in registers (20 + 5 floats).
    float w1[HHALF][IN], bb1[HHALF];
    #pragma unroll
    for (int j = 0; j < HHALF; ++j) {
        bb1[j] = b1[hbase + j];
        #pragma unroll
        for (int i = 0; i < IN; ++i) w1[j][i] = W1[(hbase + j) * IN + i];
    }
    __syncthreads();

    // State: membranes in fp regs; prev-spike as loop-carried bools
    // (predicated reset-add: skipping the add when no spike is bit-identical
    // to adding -0.0f).
    float m1[HHALF]; bool p1[HHALF];
    float m2[OUT];   bool p2[OUT];
    #pragma unroll
    for (int j = 0; j < HHALF; ++j) { m1[j] = 0.f; p1[j] = false; }
    #pragma unroll
    for (int o = 0; o < OUT; ++o)   { m2[o] = 0.f; p2[o] = false; }

    const float4* __restrict__ xp = reinterpret_cast<const float4*>(x) + e;
    // half 0 -> spk2_rec (offset 0), half 1 -> mem2_rec (offset TT*B3).
    // Strength-reduced output pointer (bumped by B3 per step).
    float* __restrict__ pout = out + (size_t)half * TT * B3 + (size_t)e * OUT;

    // Prefetch ring: x[t..t+3] resident.
    float4 xbuf[4];
    #pragma unroll
    for (int k = 0; k < 4; ++k) xbuf[k] = xp[(size_t)k * BB];

    // Layer-1 for one step: updates m1/p1, returns this half's mask bits.
    auto layer1 = [&](const float4 xv) -> unsigned {
        unsigned mk = 0;
        #pragma unroll
        for (int j = 0; j < HHALF; ++j) {
            // Ascending-k, separate mul/add roundings (no fma), bias last.
            float c = __fmul_rn(xv.x, w1[j][0]);
            c = __fadd_rn(c, __fmul_rn(xv.y, w1[j][1]));
            c = __fadd_rn(c, __fmul_rn(xv.z, w1[j][2]));
            c = __fadd_rn(c, __fmul_rn(xv.w, w1[j][3]));
            c = __fadd_rn(c, bb1[j]);
            float m = __fadd_rn(__fmul_rn(BETA, m1[j]), c); // beta*mem + cur
            if (p1[j]) m = __fadd_rn(m, -1.0f);              // @P reset (thr=1)
            const bool sp = spike_gt1(m);                    // ISETP (alu)
            p1[j] = sp;
            if (sp) mk |= (1u << (hbase + j));               // @P OR (alu)
            m1[j] = m;
        }
        return mk;
    };

    // Pipeline prologue: layer-1 of step 0.
    unsigned myMask = layer1(xbuf[0]);

    for (int t = 0; t < TT; t += 4) {
        // Prefetch x[t+4..t+7] (tail clamps to x[0..3]; those values feed
        // only the discarded junk layer-1 past step TT-1).
        const float4* xq = (t + 4 < TT) ? (xp + (size_t)(t + 4) * BB) : xp;
        float4 nxt[4];
        #pragma unroll
        for (int k = 0; k < 4; ++k) nxt[k] = xq[(size_t)k * BB];

        #pragma unroll
        for (int k = 0; k < 4; ++k) {
            // ---- step t+k: exchange masks (shfl latency in flight) ----
            const unsigned fullMask =
                myMask | __shfl_xor_sync(0xFFFFFFFFu, myMask, 1);

            // ---- layer-1 of step t+k+1 overlaps the shfl/LDS latency ----
            const float4 xnext = (k < 3) ? xbuf[k + 1] : nxt[0];
            const unsigned newMask = layer1(xnext);

            // ---- layer-2 of step t+k ----
            const float4 cv = lut[fullMask];
            const float cc[OUT] = { cv.x, cv.y, cv.z };
            #pragma unroll
            for (int o = 0; o < OUT; ++o) {
                float m = __fadd_rn(__fmul_rn(BETA, m2[o]), cc[o]);
                if (p2[o]) m = __fadd_rn(m, -1.0f);          // @P reset
                const bool sp = spike_gt1(m);                // ISETP (alu)
                p2[o] = sp;
                m2[o] = m;
                pout[o] = half ? m : (sp ? 1.0f : 0.0f);
            }
            pout += B3;                                       // pointer bump

            myMask = newMask;
        }

        #pragma unroll
        for (int k = 0; k < 4; ++k) xbuf[k] = nxt[k];
    }
}

extern "C" void kernel_launch(void* const* d_in, const int* in_sizes, int n_in,
                              void* d_out, int out_size)
{
    const float* x  = (const float*)d_in[0];   // [1000, 8192, 4]
    const float* W1 = (const float*)d_in[1];   // [10, 4]
    const float* b1 = (const float*)d_in[2];   // [10]
    const float* W2 = (const float*)d_in[3];   // [3, 10]
    const float* b2 = (const float*)d_in[4];   // [3]
    float* out = (float*)d_out;                // [spk2_rec | mem2_rec]

    snn_lif_kernel<<<(BB * 2) / 256, 256>>>(x, W1, b1, W2, b2, out);
}